// round 11
// baseline (speedup 1.0000x reference)
#include <cuda_runtime.h>
#include <cuda_fp16.h>
#include <cstdint>

// ---------------------------------------------------------------------------
// Problem constants
// ---------------------------------------------------------------------------
#define M_ROWS  32768           // B*N = 64*512
#define EMB     1024
#define NKP     17
#define APP_F   (EMB + NKP)     // 1041
#define ST_F    (4 + 3 * NKP)   // 55
#define KTOT    (APP_F + ST_F)  // 1096
#define KC      64              // fp16 K elements per pipeline chunk (128B row)
#define KPAD    1152            // 18 * 64
#define NCHUNK  (KPAD / KC)     // 18
#define TOK     1024

#define TILE_M  128
#define TILE_N  64

// SMEM: XOR-swizzled 128B rows. A tile 128 rows, B tiles 64 rows each.
#define ROWB    128
#define A_B     (128 * ROWB)            // 16384
#define B_B     (64 * ROWB)             // 8192
#define STAGE_B (A_B + 2 * B_B)         // 32768 (Ah | Bh | Bl)
#define NSTAGE  2
#define SMEM_TOTAL (NSTAGE * STAGE_B)   // 65536; x3 CTAs = 192 KB < 227 KB

// ---------------------------------------------------------------------------
// Device scratch (static globals — no allocation)
// ---------------------------------------------------------------------------
__device__ __half g_Ah[(size_t)M_ROWS * KPAD];   // fp16 features, K-major
__device__ __half g_Bh[(size_t)TOK * KPAD];      // hi half of fused weights [t][k]
__device__ __half g_Bl[(size_t)TOK * KPAD];      // lo half (B = Bh + Bl to ~2^-22)
__device__ float  g_bias[TOK];                   // app_b + st_b

// ---------------------------------------------------------------------------
// PTX helpers (baseline sm_100: ldmatrix / mma.sync / cp.async)
// ---------------------------------------------------------------------------
__device__ __forceinline__ uint32_t smem_u32(const void* p) {
    uint32_t a;
    asm("{ .reg .u64 t; cvta.to.shared.u64 t, %1; cvt.u32.u64 %0, t; }" : "=r"(a) : "l"(p));
    return a;
}

__device__ __forceinline__ void ldmx4(uint32_t* r, uint32_t addr) {
    asm volatile("ldmatrix.sync.aligned.m8n8.x4.shared.b16 {%0,%1,%2,%3}, [%4];"
                 : "=r"(r[0]), "=r"(r[1]), "=r"(r[2]), "=r"(r[3]) : "r"(addr));
}

__device__ __forceinline__ void mma16816(float* c, const uint32_t* a, const uint32_t* b) {
    asm volatile(
        "mma.sync.aligned.m16n8k16.row.col.f32.f16.f16.f32 "
        "{%0,%1,%2,%3}, {%4,%5,%6,%7}, {%8,%9}, {%0,%1,%2,%3};"
        : "+f"(c[0]), "+f"(c[1]), "+f"(c[2]), "+f"(c[3])
        : "r"(a[0]), "r"(a[1]), "r"(a[2]), "r"(a[3]), "r"(b[0]), "r"(b[1]));
}

__device__ __forceinline__ void cp16(uint32_t dst, const void* src) {
    asm volatile("cp.async.cg.shared.global [%0], [%1], 16;" :: "r"(dst), "l"(src) : "memory");
}
__device__ __forceinline__ void cp_commit() {
    asm volatile("cp.async.commit_group;" ::: "memory");
}
template <int N>
__device__ __forceinline__ void cp_wait() {
    asm volatile("cp.async.wait_group %0;" :: "n"(N) : "memory");
}

// Swizzle: 16B chunk index within a 128B row, XORed with (row & 7).
__device__ __forceinline__ uint32_t sw_off(uint32_t row, uint32_t c16) {
    return row * ROWB + ((c16 ^ (row & 7u)) << 4);
}

// ---------------------------------------------------------------------------
// Fused prologue. Blocks [0, M_ROWS): pack features row -> g_Ah (fp16).
// Blocks [M_ROWS, M_ROWS+TOK): pack weights row -> g_Bh/g_Bl + fused bias.
// ---------------------------------------------------------------------------
__global__ void prep_all(const float* __restrict__ emb, const float* __restrict__ vis,
                         const float* __restrict__ bbox, const float* __restrict__ kp,
                         const float* __restrict__ app_W, const float* __restrict__ app_b,
                         const float* __restrict__ st_W, const float* __restrict__ st_b)
{
    const int blk = blockIdx.x;
    const int tid = threadIdx.x;

    if (blk < M_ROWS) {
        const int r = blk;
        // Embedding part: thread t handles halfs [8t, 8t+8): 2x float4 -> uint4
        const float4* s = reinterpret_cast<const float4*>(emb + (size_t)r * EMB + tid * 8);
        float4 v0 = s[0], v1 = s[1];
        __half2 h0 = __floats2half2_rn(v0.x, v0.y);
        __half2 h1 = __floats2half2_rn(v0.z, v0.w);
        __half2 h2 = __floats2half2_rn(v1.x, v1.y);
        __half2 h3 = __floats2half2_rn(v1.z, v1.w);
        uint4 pk;
        pk.x = *reinterpret_cast<uint32_t*>(&h0);
        pk.y = *reinterpret_cast<uint32_t*>(&h1);
        pk.z = *reinterpret_cast<uint32_t*>(&h2);
        pk.w = *reinterpret_cast<uint32_t*>(&h3);
        *reinterpret_cast<uint4*>(g_Ah + (size_t)r * KPAD + tid * 8) = pk;
        // Tail part: k in [1024, 1152)
        const int k = EMB + tid;
        float v = 0.0f;
        if (k < APP_F)          v = vis[(size_t)r * NKP + (k - EMB)];
        else if (k < APP_F + 4) v = bbox[(size_t)r * 4 + (k - APP_F)];
        else if (k < KTOT)      v = kp[(size_t)r * (3 * NKP) + (k - APP_F - 4)];
        g_Ah[(size_t)r * KPAD + k] = __float2half_rn(v);
    } else {
        const int t = blk - M_ROWS;
        if (tid == 0) g_bias[t] = app_b[t] + st_b[t];
        for (int k = tid; k < KPAD; k += 128) {
            float v = 0.0f;
            if (k < APP_F)      v = app_W[t * APP_F + k];
            else if (k < KTOT)  v = st_W[t * ST_F + (k - APP_F)];
            __half h = __float2half_rn(v);
            g_Bh[(size_t)t * KPAD + k] = h;
            g_Bl[(size_t)t * KPAD + k] = __float2half_rn(v - __half2float(h));
        }
    }
}

// ---------------------------------------------------------------------------
// Main GEMM: one-sided fp16 split  C = Ah*Bh + Ah*Bl  (fp32 accumulate).
// 128x64 CTA tile, 8 warps (warp tile 64x16), K-chunks of 64, swizzled SMEM,
// 2-stage cp.async pipeline, 3 CTAs/SM (24 warps) for latency hiding.
// ---------------------------------------------------------------------------
__global__ void __launch_bounds__(256, 3)
gemm_hmma(const unsigned int* __restrict__ mask, float* __restrict__ out)
{
    extern __shared__ __align__(128) char smem[];
    const uint32_t sb = smem_u32(smem);

    const int tid    = threadIdx.x;
    const int lane   = tid & 31;
    const int wid    = tid >> 5;
    const int warp_m = (wid & 1) * 64;      // 2 warps along M
    const int warp_n = (wid >> 1) * 16;     // 4 warps along N
    const int row0   = blockIdx.y * TILE_M;
    const int col0   = blockIdx.x * TILE_N;

    // Loader mapping: one full 128B row per thread (8 cp.async each).
    //   tid [0,128)   -> A row tid
    //   tid [128,192) -> Bh row tid-128
    //   tid [192,256) -> Bl row tid-192
    const int which = tid >> 7;                     // 0 = A, 1 = B
    const int bsel  = (tid >> 6) & 1;               // within B: 0 = Bh, 1 = Bl
    const int lrow  = which ? (tid & 63) : (tid & 127);
    const __half* gsrc = which ? (bsel ? g_Bl : g_Bh) : g_Ah;
    const size_t  goff = which ? (size_t)(col0 + lrow) * KPAD
                               : (size_t)(row0 + lrow) * KPAD;
    const uint32_t dbase = which ? (uint32_t)(A_B + bsel * B_B) : 0u;

    float acc[4][2][4];
    #pragma unroll
    for (int i = 0; i < 4; i++)
        #pragma unroll
        for (int j = 0; j < 2; j++)
            #pragma unroll
            for (int q = 0; q < 4; q++) acc[i][j][q] = 0.0f;

    // ---- async-load one 64-deep K chunk into a stage buffer
    auto cpAll = [&](int s, uint32_t buf) {
        const int k0 = s * KC;
        const __half* src = gsrc + goff + k0;
        const uint32_t d = buf + dbase;
        #pragma unroll
        for (int c = 0; c < 8; c++)
            cp16(d + sw_off((uint32_t)lrow, (uint32_t)c), src + c * 8);
    };

    // ---- compute one 64-deep K chunk from a stage buffer
    auto compute = [&](uint32_t buf) {
        const uint32_t aH = buf;
        const uint32_t bH = buf + A_B, bL = buf + A_B + B_B;
        const uint32_t arow = (uint32_t)(lane & 15);
        const uint32_t nrow = (uint32_t)((lane & 7) + ((lane >> 4) << 3));
        #pragma unroll
        for (int k16 = 0; k16 < 4; k16++) {
            const uint32_t ac = (uint32_t)(k16 * 2 + (lane >> 4));
            const uint32_t bc = (uint32_t)(k16 * 2 + ((lane & 8) >> 3));
            uint32_t Ah[4][4], Bh[2][2], Bl[2][2];
            #pragma unroll
            for (int am = 0; am < 4; am++)
                ldmx4(Ah[am], aH + sw_off((uint32_t)(warp_m + am * 16) + arow, ac));
            {
                const uint32_t ro = sw_off((uint32_t)warp_n + nrow, bc);
                uint32_t r[4];
                ldmx4(r, bH + ro);
                Bh[0][0]=r[0]; Bh[0][1]=r[1]; Bh[1][0]=r[2]; Bh[1][1]=r[3];
                ldmx4(r, bL + ro);
                Bl[0][0]=r[0]; Bl[0][1]=r[1]; Bl[1][0]=r[2]; Bl[1][1]=r[3];
            }
            #pragma unroll
            for (int am = 0; am < 4; am++)
                #pragma unroll
                for (int an = 0; an < 2; an++) {
                    mma16816(acc[am][an], Ah[am], Bh[an]);
                    mma16816(acc[am][an], Ah[am], Bl[an]);
                }
        }
    };

    // ---- 2-stage pipeline, prefetch distance 1
    cpAll(0, sb); cp_commit();

    for (int s = 0; s < NCHUNK; s++) {
        if (s + 1 < NCHUNK) {
            cpAll(s + 1, sb + (uint32_t)((s + 1) & 1) * STAGE_B);
            cp_commit();
            cp_wait<1>();       // chunk s complete (chunk s+1 may remain in flight)
        } else {
            cp_wait<0>();
        }
        __syncthreads();        // chunk s visible to all warps
        compute(sb + (uint32_t)(s & 1) * STAGE_B);
        __syncthreads();        // all warps done with stage s&1 before overwrite
    }

    // ---- epilogue: bias + row mask, float2 stores straight from accumulators
    #pragma unroll
    for (int am = 0; am < 4; am++) {
        const int r1 = row0 + warp_m + am * 16 + (lane >> 2);
        const int r2 = r1 + 8;
        const bool m1 = (mask[r1] != 0u);
        const bool m2 = (mask[r2] != 0u);
        #pragma unroll
        for (int an = 0; an < 2; an++) {
            const int cc = col0 + warp_n + an * 8 + 2 * (lane & 3);
            const float b0 = g_bias[cc], b1 = g_bias[cc + 1];
            float2 v1, v2;
            v1.x = m1 ? acc[am][an][0] + b0 : 0.0f;
            v1.y = m1 ? acc[am][an][1] + b1 : 0.0f;
            v2.x = m2 ? acc[am][an][2] + b0 : 0.0f;
            v2.y = m2 ? acc[am][an][3] + b1 : 0.0f;
            *reinterpret_cast<float2*>(out + (size_t)r1 * TOK + cc) = v1;
            *reinterpret_cast<float2*>(out + (size_t)r2 * TOK + cc) = v2;
        }
    }
}

// ---------------------------------------------------------------------------
extern "C" void kernel_launch(void* const* d_in, const int* in_sizes, int n_in,
                              void* d_out, int out_size)
{
    const float*        emb   = (const float*)d_in[0];
    const float*        vis   = (const float*)d_in[1];
    const float*        bbox  = (const float*)d_in[2];
    const float*        kp    = (const float*)d_in[3];
    const unsigned int* mask  = (const unsigned int*)d_in[4];
    const float*        app_W = (const float*)d_in[5];
    const float*        app_b = (const float*)d_in[6];
    const float*        st_W  = (const float*)d_in[7];
    const float*        st_b  = (const float*)d_in[8];
    float*              out   = (float*)d_out;

    cudaFuncSetAttribute(gemm_hmma, cudaFuncAttributeMaxDynamicSharedMemorySize, SMEM_TOTAL);

    prep_all<<<M_ROWS + TOK, 128>>>(emb, vis, bbox, kp, app_W, app_b, st_W, st_b);

    dim3 grid(TOK / TILE_N, M_ROWS / TILE_M);   // (16, 256): col-fastest -> A-tile L2 reuse
    gemm_hmma<<<grid, 256, SMEM_TOTAL>>>(mask, out);
}

// round 15
// speedup vs baseline: 1.7297x; 1.7297x over previous
#include <cuda_runtime.h>
#include <cuda_fp16.h>
#include <cstdint>

// ---------------------------------------------------------------------------
// Problem constants
// ---------------------------------------------------------------------------
#define M_ROWS  32768           // B*N = 64*512
#define EMB     1024
#define NKP     17
#define APP_F   (EMB + NKP)     // 1041
#define ST_F    (4 + 3 * NKP)   // 55
#define KTOT    (APP_F + ST_F)  // 1096
#define KC      64              // fp16 K elements per chunk (128B row)
#define KPAD    1152            // 18 * 64
#define NCHUNK  (KPAD / KC)     // 18
#define TOK     1024

#define TILE_M  256
#define TILE_N  128
#define NMTILE  (M_ROWS / TILE_M)   // 128
#define NNTILE  (TOK / TILE_N)      // 8

// Tiled-global + SMEM layout (pre-swizzled blobs):
//   A chunk tile: 256 rows x 128B = 32 KB;  B chunk tile: 128 rows x 128B = 16 KB
#define ROWB    128
#define A_TB    32768
#define B_TB    16384
#define STAGE_B (A_TB + 2 * B_TB)       // A | Bh | Bl = 65536
#define SMEM_TOTAL (2 * STAGE_B)        // 131072 B (1 CTA/SM)

// ---------------------------------------------------------------------------
// Device scratch (static globals — no allocation). Tiled, PRE-SWIZZLED:
//   g_Ah: [mtile(128)][chunk(18)][32KB],  g_Bh/g_Bl: [ntile(8)][chunk(18)][16KB]
// ---------------------------------------------------------------------------
__device__ __half g_Ah[(size_t)M_ROWS * KPAD];
__device__ __half g_Bh[(size_t)TOK * KPAD];
__device__ __half g_Bl[(size_t)TOK * KPAD];
__device__ float  g_bias[TOK];

// ---------------------------------------------------------------------------
// PTX helpers (proven set only: ldmatrix / mma.sync / cp.async)
// ---------------------------------------------------------------------------
__device__ __forceinline__ uint32_t smem_u32(const void* p) {
    uint32_t a;
    asm("{ .reg .u64 t; cvta.to.shared.u64 t, %1; cvt.u32.u64 %0, t; }" : "=r"(a) : "l"(p));
    return a;
}

__device__ __forceinline__ void ldmx4(uint32_t* r, uint32_t addr) {
    asm volatile("ldmatrix.sync.aligned.m8n8.x4.shared.b16 {%0,%1,%2,%3}, [%4];"
                 : "=r"(r[0]), "=r"(r[1]), "=r"(r[2]), "=r"(r[3]) : "r"(addr));
}

__device__ __forceinline__ void mma16816(float* c, const uint32_t* a, const uint32_t* b) {
    asm volatile(
        "mma.sync.aligned.m16n8k16.row.col.f32.f16.f16.f32 "
        "{%0,%1,%2,%3}, {%4,%5,%6,%7}, {%8,%9}, {%0,%1,%2,%3};"
        : "+f"(c[0]), "+f"(c[1]), "+f"(c[2]), "+f"(c[3])
        : "r"(a[0]), "r"(a[1]), "r"(a[2]), "r"(a[3]), "r"(b[0]), "r"(b[1]));
}

__device__ __forceinline__ void cp16(uint32_t dst, const void* src) {
    asm volatile("cp.async.cg.shared.global [%0], [%1], 16;" :: "r"(dst), "l"(src) : "memory");
}
__device__ __forceinline__ void cp_commit() {
    asm volatile("cp.async.commit_group;" ::: "memory");
}
template <int N>
__device__ __forceinline__ void cp_wait() {
    asm volatile("cp.async.wait_group %0;" :: "n"(N) : "memory");
}

// Swizzle: 16B chunk index within a 128B row, XORed with (row & 7).
__device__ __forceinline__ uint32_t sw_off(uint32_t row, uint32_t c16) {
    return row * ROWB + ((c16 ^ (row & 7u)) << 4);
}

// ---------------------------------------------------------------------------
// Fused prologue, writing the TILED + PRE-SWIZZLED global layout.
// Blocks [0, M_ROWS): one feature row -> its 18 chunk slots in g_Ah.
// Blocks [M_ROWS, +TOK): one weight row -> g_Bh/g_Bl slots + fused bias.
// ---------------------------------------------------------------------------
__global__ void prep_all(const float* __restrict__ emb, const float* __restrict__ vis,
                         const float* __restrict__ bbox, const float* __restrict__ kp,
                         const float* __restrict__ app_W, const float* __restrict__ app_b,
                         const float* __restrict__ st_W, const float* __restrict__ st_b)
{
    const int blk = blockIdx.x;
    const int tid = threadIdx.x;
    char* const AhB = reinterpret_cast<char*>(g_Ah);
    char* const BhB = reinterpret_cast<char*>(g_Bh);
    char* const BlB = reinterpret_cast<char*>(g_Bl);

    if (blk < M_ROWS) {
        const int r = blk;
        const int mtile = r >> 8, mrow = r & 255;       // 256-row A tiles
        const size_t tb0 = (size_t)mtile * NCHUNK * A_TB;
        // Embedding: thread t packs halfs [8t, 8t+8) -> one swizzled 16B slot
        const float4* s = reinterpret_cast<const float4*>(emb + (size_t)r * EMB + tid * 8);
        float4 v0 = s[0], v1 = s[1];
        __half2 h0 = __floats2half2_rn(v0.x, v0.y);
        __half2 h1 = __floats2half2_rn(v0.z, v0.w);
        __half2 h2 = __floats2half2_rn(v1.x, v1.y);
        __half2 h3 = __floats2half2_rn(v1.z, v1.w);
        uint4 pk;
        pk.x = *reinterpret_cast<uint32_t*>(&h0);
        pk.y = *reinterpret_cast<uint32_t*>(&h1);
        pk.z = *reinterpret_cast<uint32_t*>(&h2);
        pk.w = *reinterpret_cast<uint32_t*>(&h3);
        const int c = tid >> 3;                         // chunk = (8t)/64
        const uint32_t c16 = (uint32_t)(tid & 7);
        *reinterpret_cast<uint4*>(AhB + tb0 + (size_t)c * A_TB
                                  + sw_off((uint32_t)mrow, c16)) = pk;
        // Tail: k in [1024, 1152), one half per thread
        const int k = EMB + tid;
        float v = 0.0f;
        if (k < APP_F)          v = vis[(size_t)r * NKP + (k - EMB)];
        else if (k < APP_F + 4) v = bbox[(size_t)r * 4 + (k - APP_F)];
        else if (k < KTOT)      v = kp[(size_t)r * (3 * NKP) + (k - APP_F - 4)];
        const int ct = k >> 6, kc = k & 63;
        *reinterpret_cast<__half*>(AhB + tb0 + (size_t)ct * A_TB
                                   + sw_off((uint32_t)mrow, (uint32_t)(kc >> 3))
                                   + (kc & 7) * 2) = __float2half_rn(v);
    } else {
        const int t = blk - M_ROWS;
        const int ntile = t >> 7, nrow = t & 127;       // 128-row B tiles
        const size_t tb0 = (size_t)ntile * NCHUNK * B_TB;
        if (tid == 0) g_bias[t] = app_b[t] + st_b[t];
        for (int k = tid; k < KPAD; k += 128) {
            float v = 0.0f;
            if (k < APP_F)      v = app_W[t * APP_F + k];
            else if (k < KTOT)  v = st_W[t * ST_F + (k - APP_F)];
            __half h = __float2half_rn(v);
            __half l = __float2half_rn(v - __half2float(h));
            const int c = k >> 6, kc = k & 63;
            const size_t off = tb0 + (size_t)c * B_TB
                             + sw_off((uint32_t)nrow, (uint32_t)(kc >> 3)) + (kc & 7) * 2;
            *reinterpret_cast<__half*>(BhB + off) = h;
            *reinterpret_cast<__half*>(BlB + off) = l;
        }
    }
}

// ---------------------------------------------------------------------------
// Main GEMM: one-sided fp16 split  C = Ah*Bh + Ah*Bl  (fp32 accumulate).
// 256x128 CTA tile, 512 threads, 16 warps (64x32 warp tile, 4x4 warp grid).
// Loader: contiguous 16B cp.async from pre-swizzled tile blobs (zero address
// math), 2-stage pipeline.
// ---------------------------------------------------------------------------
__global__ void __launch_bounds__(512, 1)
gemm_hmma(const unsigned int* __restrict__ mask, float* __restrict__ out)
{
    extern __shared__ __align__(128) char smem[];
    const uint32_t sb = smem_u32(smem);

    const int tid    = threadIdx.x;
    const int lane   = tid & 31;
    const int wid    = tid >> 5;
    const int warp_m = (wid & 3) * 64;      // 4 warps along M
    const int warp_n = (wid >> 2) * 32;     // 4 warps along N
    const int row0   = blockIdx.y * TILE_M;
    const int col0   = blockIdx.x * TILE_N;

    const char* const pA  = reinterpret_cast<const char*>(g_Ah)
                          + (size_t)blockIdx.y * NCHUNK * A_TB;
    const char* const pBh = reinterpret_cast<const char*>(g_Bh)
                          + (size_t)blockIdx.x * NCHUNK * B_TB;
    const char* const pBl = reinterpret_cast<const char*>(g_Bl)
                          + (size_t)blockIdx.x * NCHUNK * B_TB;

    float acc[4][4][4];
    #pragma unroll
    for (int i = 0; i < 4; i++)
        #pragma unroll
        for (int j = 0; j < 4; j++)
            #pragma unroll
            for (int q = 0; q < 4; q++) acc[i][j][q] = 0.0f;

    // ---- async-load one 64-deep K chunk: contiguous copy, dst_off == src_off
    //   A: 32 KB -> 64 B/thread (4 cp16);  Bh/Bl: 16 KB -> 32 B/thread (2 cp16)
    auto cpAll = [&](int s, uint32_t buf) {
        {
            const char* sa = pA + (size_t)s * A_TB + tid * 64;
            const uint32_t da = buf + (uint32_t)tid * 64;
            #pragma unroll
            for (int i = 0; i < 4; i++) cp16(da + i * 16, sa + i * 16);
        }
        {
            const char* sh = pBh + (size_t)s * B_TB + tid * 32;
            const char* sl = pBl + (size_t)s * B_TB + tid * 32;
            const uint32_t dh = buf + A_TB + (uint32_t)tid * 32;
            const uint32_t dl = buf + A_TB + B_TB + (uint32_t)tid * 32;
            cp16(dh, sh); cp16(dh + 16, sh + 16);
            cp16(dl, sl); cp16(dl + 16, sl + 16);
        }
    };

    // ---- compute one 64-deep K chunk (R10-proven fragment path)
    auto compute = [&](uint32_t buf) {
        const uint32_t aH = buf;
        const uint32_t bH = buf + A_TB, bL = buf + A_TB + B_TB;
        const uint32_t arow = (uint32_t)(lane & 15);
        const uint32_t nrow = (uint32_t)((lane & 7) + ((lane >> 4) << 3));
        #pragma unroll
        for (int k16 = 0; k16 < 4; k16++) {
            const uint32_t ac = (uint32_t)(k16 * 2 + (lane >> 4));
            const uint32_t bc = (uint32_t)(k16 * 2 + ((lane & 8) >> 3));
            uint32_t Ah[4][4], Bh[4][2], Bl[4][2];
            #pragma unroll
            for (int am = 0; am < 4; am++)
                ldmx4(Ah[am], aH + sw_off((uint32_t)(warp_m + am * 16) + arow, ac));
            #pragma unroll
            for (int bp = 0; bp < 2; bp++) {
                const uint32_t ro = sw_off((uint32_t)(warp_n + bp * 16) + nrow, bc);
                uint32_t r[4];
                ldmx4(r, bH + ro);
                Bh[bp*2][0]=r[0]; Bh[bp*2][1]=r[1]; Bh[bp*2+1][0]=r[2]; Bh[bp*2+1][1]=r[3];
                ldmx4(r, bL + ro);
                Bl[bp*2][0]=r[0]; Bl[bp*2][1]=r[1]; Bl[bp*2+1][0]=r[2]; Bl[bp*2+1][1]=r[3];
            }
            #pragma unroll
            for (int am = 0; am < 4; am++)
                #pragma unroll
                for (int an = 0; an < 4; an++) {
                    mma16816(acc[am][an], Ah[am], Bh[an]);
                    mma16816(acc[am][an], Ah[am], Bl[an]);
                }
        }
    };

    // ---- 2-stage pipeline, prefetch distance 1 (R10-proven cadence)
    cpAll(0, sb); cp_commit();

    for (int s = 0; s < NCHUNK; s++) {
        if (s + 1 < NCHUNK) {
            cpAll(s + 1, sb + (uint32_t)((s + 1) & 1) * STAGE_B);
            cp_commit();
            cp_wait<1>();       // chunk s complete (chunk s+1 may remain in flight)
        } else {
            cp_wait<0>();
        }
        __syncthreads();        // chunk s visible to all warps
        compute(sb + (uint32_t)(s & 1) * STAGE_B);
        __syncthreads();        // all warps done with stage s&1 before overwrite
    }

    // ---- epilogue: bias + row mask, float2 stores straight from accumulators
    #pragma unroll
    for (int am = 0; am < 4; am++) {
        const int r1 = row0 + warp_m + am * 16 + (lane >> 2);
        const int r2 = r1 + 8;
        const bool m1 = (mask[r1] != 0u);
        const bool m2 = (mask[r2] != 0u);
        #pragma unroll
        for (int an = 0; an < 4; an++) {
            const int cc = col0 + warp_n + an * 8 + 2 * (lane & 3);
            const float b0 = g_bias[cc], b1 = g_bias[cc + 1];
            float2 v1, v2;
            v1.x = m1 ? acc[am][an][0] + b0 : 0.0f;
            v1.y = m1 ? acc[am][an][1] + b1 : 0.0f;
            v2.x = m2 ? acc[am][an][2] + b0 : 0.0f;
            v2.y = m2 ? acc[am][an][3] + b1 : 0.0f;
            *reinterpret_cast<float2*>(out + (size_t)r1 * TOK + cc) = v1;
            *reinterpret_cast<float2*>(out + (size_t)r2 * TOK + cc) = v2;
        }
    }
}

// ---------------------------------------------------------------------------
extern "C" void kernel_launch(void* const* d_in, const int* in_sizes, int n_in,
                              void* d_out, int out_size)
{
    const float*        emb   = (const float*)d_in[0];
    const float*        vis   = (const float*)d_in[1];
    const float*        bbox  = (const float*)d_in[2];
    const float*        kp    = (const float*)d_in[3];
    const unsigned int* mask  = (const unsigned int*)d_in[4];
    const float*        app_W = (const float*)d_in[5];
    const float*        app_b = (const float*)d_in[6];
    const float*        st_W  = (const float*)d_in[7];
    const float*        st_b  = (const float*)d_in[8];
    float*              out   = (float*)d_out;

    cudaFuncSetAttribute(gemm_hmma, cudaFuncAttributeMaxDynamicSharedMemorySize, SMEM_TOTAL);

    prep_all<<<M_ROWS + TOK, 128>>>(emb, vis, bbox, kp, app_W, app_b, st_W, st_b);

    dim3 grid(NNTILE, NMTILE);   // (8, 128): col-fastest -> A-tile L2 reuse
    gemm_hmma<<<grid, 256 * 2, SMEM_TOTAL>>>(mask, out);
}

// round 16
// speedup vs baseline: 2.6687x; 1.5429x over previous
#include <cuda_runtime.h>
#include <cuda_fp16.h>
#include <cstdint>

// ---------------------------------------------------------------------------
// Problem constants
// ---------------------------------------------------------------------------
#define M_ROWS  32768           // B*N = 64*512
#define EMB     1024
#define NKP     17
#define APP_F   (EMB + NKP)     // 1041
#define ST_F    (4 + 3 * NKP)   // 55
#define KTOT    (APP_F + ST_F)  // 1096
#define KC      64              // fp16 K elements per chunk (128B row)
#define KPAD    1152            // 18 * 64
#define NCHUNK  (KPAD / KC)     // 18
#define TOK     1024

#define TILE_M  256
#define TILE_N  128
#define NMTILE  (M_ROWS / TILE_M)   // 128
#define NNTILE  (TOK / TILE_N)      // 8

// Tiled-global + SMEM layout (pre-swizzled blobs):
//   A chunk tile: 256 rows x 128B = 32 KB;  B chunk tile: 128 rows x 128B = 16 KB
#define ROWB    128
#define A_TB    32768
#define B_TB    16384
#define STAGE_B (A_TB + B_TB)           // A | Bh = 49152
#define NSTAGE  4
#define SMEM_TOTAL (NSTAGE * STAGE_B)   // 196608 B (1 CTA/SM)

// ---------------------------------------------------------------------------
// Device scratch (static globals — no allocation). Tiled, PRE-SWIZZLED:
//   g_Ah: [mtile(128)][chunk(18)][32KB],  g_Bh: [ntile(8)][chunk(18)][16KB]
// ---------------------------------------------------------------------------
__device__ __half g_Ah[(size_t)M_ROWS * KPAD];
__device__ __half g_Bh[(size_t)TOK * KPAD];
__device__ float  g_bias[TOK];

// ---------------------------------------------------------------------------
// PTX helpers (proven set only: ldmatrix / mma.sync / cp.async)
// ---------------------------------------------------------------------------
__device__ __forceinline__ uint32_t smem_u32(const void* p) {
    uint32_t a;
    asm("{ .reg .u64 t; cvta.to.shared.u64 t, %1; cvt.u32.u64 %0, t; }" : "=r"(a) : "l"(p));
    return a;
}

__device__ __forceinline__ void ldmx4(uint32_t* r, uint32_t addr) {
    asm volatile("ldmatrix.sync.aligned.m8n8.x4.shared.b16 {%0,%1,%2,%3}, [%4];"
                 : "=r"(r[0]), "=r"(r[1]), "=r"(r[2]), "=r"(r[3]) : "r"(addr));
}

__device__ __forceinline__ void mma16816(float* c, const uint32_t* a, const uint32_t* b) {
    asm volatile(
        "mma.sync.aligned.m16n8k16.row.col.f32.f16.f16.f32 "
        "{%0,%1,%2,%3}, {%4,%5,%6,%7}, {%8,%9}, {%0,%1,%2,%3};"
        : "+f"(c[0]), "+f"(c[1]), "+f"(c[2]), "+f"(c[3])
        : "r"(a[0]), "r"(a[1]), "r"(a[2]), "r"(a[3]), "r"(b[0]), "r"(b[1]));
}

__device__ __forceinline__ void cp16(uint32_t dst, const void* src) {
    asm volatile("cp.async.cg.shared.global [%0], [%1], 16;" :: "r"(dst), "l"(src) : "memory");
}
__device__ __forceinline__ void cp_commit() {
    asm volatile("cp.async.commit_group;" ::: "memory");
}
template <int N>
__device__ __forceinline__ void cp_wait() {
    asm volatile("cp.async.wait_group %0;" :: "n"(N) : "memory");
}

// Swizzle: 16B chunk index within a 128B row, XORed with (row & 7).
__device__ __forceinline__ uint32_t sw_off(uint32_t row, uint32_t c16) {
    return row * ROWB + ((c16 ^ (row & 7u)) << 4);
}

// ---------------------------------------------------------------------------
// Fused prologue, writing the TILED + PRE-SWIZZLED global layout.
// Blocks [0, M_ROWS): one feature row -> its 18 chunk slots in g_Ah.
// Blocks [M_ROWS, +TOK): one weight row -> g_Bh slots + fused bias.
// ---------------------------------------------------------------------------
__global__ void prep_all(const float* __restrict__ emb, const float* __restrict__ vis,
                         const float* __restrict__ bbox, const float* __restrict__ kp,
                         const float* __restrict__ app_W, const float* __restrict__ app_b,
                         const float* __restrict__ st_W, const float* __restrict__ st_b)
{
    const int blk = blockIdx.x;
    const int tid = threadIdx.x;
    char* const AhB = reinterpret_cast<char*>(g_Ah);
    char* const BhB = reinterpret_cast<char*>(g_Bh);

    if (blk < M_ROWS) {
        const int r = blk;
        const int mtile = r >> 8, mrow = r & 255;       // 256-row A tiles
        const size_t tb0 = (size_t)mtile * NCHUNK * A_TB;
        // Embedding: thread t packs halfs [8t, 8t+8) -> one swizzled 16B slot
        const float4* s = reinterpret_cast<const float4*>(emb + (size_t)r * EMB + tid * 8);
        float4 v0 = s[0], v1 = s[1];
        __half2 h0 = __floats2half2_rn(v0.x, v0.y);
        __half2 h1 = __floats2half2_rn(v0.z, v0.w);
        __half2 h2 = __floats2half2_rn(v1.x, v1.y);
        __half2 h3 = __floats2half2_rn(v1.z, v1.w);
        uint4 pk;
        pk.x = *reinterpret_cast<uint32_t*>(&h0);
        pk.y = *reinterpret_cast<uint32_t*>(&h1);
        pk.z = *reinterpret_cast<uint32_t*>(&h2);
        pk.w = *reinterpret_cast<uint32_t*>(&h3);
        const int c = tid >> 3;                         // chunk = (8t)/64
        const uint32_t c16 = (uint32_t)(tid & 7);
        *reinterpret_cast<uint4*>(AhB + tb0 + (size_t)c * A_TB
                                  + sw_off((uint32_t)mrow, c16)) = pk;
        // Tail: k in [1024, 1152), one half per thread
        const int k = EMB + tid;
        float v = 0.0f;
        if (k < APP_F)          v = vis[(size_t)r * NKP + (k - EMB)];
        else if (k < APP_F + 4) v = bbox[(size_t)r * 4 + (k - APP_F)];
        else if (k < KTOT)      v = kp[(size_t)r * (3 * NKP) + (k - APP_F - 4)];
        const int ct = k >> 6, kc = k & 63;
        *reinterpret_cast<__half*>(AhB + tb0 + (size_t)ct * A_TB
                                   + sw_off((uint32_t)mrow, (uint32_t)(kc >> 3))
                                   + (kc & 7) * 2) = __float2half_rn(v);
    } else {
        const int t = blk - M_ROWS;
        const int ntile = t >> 7, nrow = t & 127;       // 128-row B tiles
        const size_t tb0 = (size_t)ntile * NCHUNK * B_TB;
        if (tid == 0) g_bias[t] = app_b[t] + st_b[t];
        for (int k = tid; k < KPAD; k += 128) {
            float v = 0.0f;
            if (k < APP_F)      v = app_W[t * APP_F + k];
            else if (k < KTOT)  v = st_W[t * ST_F + (k - APP_F)];
            const int c = k >> 6, kc = k & 63;
            *reinterpret_cast<__half*>(BhB + tb0 + (size_t)c * B_TB
                                       + sw_off((uint32_t)nrow, (uint32_t)(kc >> 3))
                                       + (kc & 7) * 2) = __float2half_rn(v);
        }
    }
}

// ---------------------------------------------------------------------------
// Main GEMM: fp16 x fp16 -> fp32 accumulate (A and B both round-to-nearest
// fp16; measured independent error sources ~2e-4 each => ~2.9e-4 combined).
// 256x128 CTA tile, 512 threads, 16 warps (64x32 warp tile, 4x4 warp grid).
// Loader: contiguous 16B cp.async from pre-swizzled tile blobs.
// 4-stage pipeline, prefetch distance 3, ONE barrier per chunk.
// ---------------------------------------------------------------------------
__global__ void __launch_bounds__(512, 1)
gemm_hmma(const unsigned int* __restrict__ mask, float* __restrict__ out)
{
    extern __shared__ __align__(128) char smem[];
    const uint32_t sb = smem_u32(smem);

    const int tid    = threadIdx.x;
    const int lane   = tid & 31;
    const int wid    = tid >> 5;
    const int warp_m = (wid & 3) * 64;      // 4 warps along M
    const int warp_n = (wid >> 2) * 32;     // 4 warps along N
    const int row0   = blockIdx.y * TILE_M;
    const int col0   = blockIdx.x * TILE_N;

    const char* const pA  = reinterpret_cast<const char*>(g_Ah)
                          + (size_t)blockIdx.y * NCHUNK * A_TB;
    const char* const pBh = reinterpret_cast<const char*>(g_Bh)
                          + (size_t)blockIdx.x * NCHUNK * B_TB;

    float acc[4][4][4];
    #pragma unroll
    for (int i = 0; i < 4; i++)
        #pragma unroll
        for (int j = 0; j < 4; j++)
            #pragma unroll
            for (int q = 0; q < 4; q++) acc[i][j][q] = 0.0f;

    // ---- async-load one 64-deep K chunk: contiguous copy, dst_off == src_off
    //   A: 32 KB -> 64 B/thread (4 cp16);  Bh: 16 KB -> 32 B/thread (2 cp16)
    auto cpAll = [&](int s, uint32_t buf) {
        {
            const char* sa = pA + (size_t)s * A_TB + tid * 64;
            const uint32_t da = buf + (uint32_t)tid * 64;
            #pragma unroll
            for (int i = 0; i < 4; i++) cp16(da + i * 16, sa + i * 16);
        }
        {
            const char* sh = pBh + (size_t)s * B_TB + tid * 32;
            const uint32_t dh = buf + A_TB + (uint32_t)tid * 32;
            cp16(dh, sh); cp16(dh + 16, sh + 16);
        }
    };

    // ---- compute one 64-deep K chunk
    auto compute = [&](uint32_t buf) {
        const uint32_t aH = buf;
        const uint32_t bH = buf + A_TB;
        const uint32_t arow = (uint32_t)(lane & 15);
        const uint32_t nrow = (uint32_t)((lane & 7) + ((lane >> 4) << 3));
        #pragma unroll
        for (int k16 = 0; k16 < 4; k16++) {
            const uint32_t ac = (uint32_t)(k16 * 2 + (lane >> 4));
            const uint32_t bc = (uint32_t)(k16 * 2 + ((lane & 8) >> 3));
            uint32_t Ah[4][4], Bh[4][2];
            #pragma unroll
            for (int am = 0; am < 4; am++)
                ldmx4(Ah[am], aH + sw_off((uint32_t)(warp_m + am * 16) + arow, ac));
            #pragma unroll
            for (int bp = 0; bp < 2; bp++) {
                const uint32_t ro = sw_off((uint32_t)(warp_n + bp * 16) + nrow, bc);
                uint32_t r[4];
                ldmx4(r, bH + ro);
                Bh[bp*2][0]=r[0]; Bh[bp*2][1]=r[1]; Bh[bp*2+1][0]=r[2]; Bh[bp*2+1][1]=r[3];
            }
            #pragma unroll
            for (int am = 0; am < 4; am++)
                #pragma unroll
                for (int an = 0; an < 4; an++)
                    mma16816(acc[am][an], Ah[am], Bh[an]);
        }
    };

    // ---- 4-stage pipeline, prefetch distance 3, single barrier per chunk.
    cpAll(0, sb + 0 * STAGE_B); cp_commit();
    cpAll(1, sb + 1 * STAGE_B); cp_commit();
    cpAll(2, sb + 2 * STAGE_B); cp_commit();

    for (int s = 0; s < NCHUNK; s++) {
        cp_wait<2>();           // groups are 1-per-iter (empty ones too): chunk s done
        __syncthreads();        // all warps finished compute(s-1) -> stage (s-1)%4 free
        if (s + 3 < NCHUNK)
            cpAll(s + 3, sb + (uint32_t)((s + 3) % NSTAGE) * STAGE_B);
        cp_commit();            // unconditional: keeps outstanding-group count invariant
        compute(sb + (uint32_t)(s % NSTAGE) * STAGE_B);
    }

    // ---- epilogue: bias + row mask, float2 stores straight from accumulators
    #pragma unroll
    for (int am = 0; am < 4; am++) {
        const int r1 = row0 + warp_m + am * 16 + (lane >> 2);
        const int r2 = r1 + 8;
        const bool m1 = (mask[r1] != 0u);
        const bool m2 = (mask[r2] != 0u);
        #pragma unroll
        for (int an = 0; an < 4; an++) {
            const int cc = col0 + warp_n + an * 8 + 2 * (lane & 3);
            const float b0 = g_bias[cc], b1 = g_bias[cc + 1];
            float2 v1, v2;
            v1.x = m1 ? acc[am][an][0] + b0 : 0.0f;
            v1.y = m1 ? acc[am][an][1] + b1 : 0.0f;
            v2.x = m2 ? acc[am][an][2] + b0 : 0.0f;
            v2.y = m2 ? acc[am][an][3] + b1 : 0.0f;
            *reinterpret_cast<float2*>(out + (size_t)r1 * TOK + cc) = v1;
            *reinterpret_cast<float2*>(out + (size_t)r2 * TOK + cc) = v2;
        }
    }
}

// ---------------------------------------------------------------------------
extern "C" void kernel_launch(void* const* d_in, const int* in_sizes, int n_in,
                              void* d_out, int out_size)
{
    const float*        emb   = (const float*)d_in[0];
    const float*        vis   = (const float*)d_in[1];
    const float*        bbox  = (const float*)d_in[2];
    const float*        kp    = (const float*)d_in[3];
    const unsigned int* mask  = (const unsigned int*)d_in[4];
    const float*        app_W = (const float*)d_in[5];
    const float*        app_b = (const float*)d_in[6];
    const float*        st_W  = (const float*)d_in[7];
    const float*        st_b  = (const float*)d_in[8];
    float*              out   = (float*)d_out;

    cudaFuncSetAttribute(gemm_hmma, cudaFuncAttributeMaxDynamicSharedMemorySize, SMEM_TOTAL);

    prep_all<<<M_ROWS + TOK, 128>>>(emb, vis, bbox, kp, app_W, app_b, st_W, st_b);

    dim3 grid(NNTILE, NMTILE);   // (8, 128): col-fastest -> A-tile L2 reuse
    gemm_hmma<<<grid, 512, SMEM_TOTAL>>>(mask, out);
}

// round 17
// speedup vs baseline: 3.1177x; 1.1683x over previous
#include <cuda_runtime.h>
#include <cuda_fp16.h>
#include <cstdint>

// ---------------------------------------------------------------------------
// Problem constants
// ---------------------------------------------------------------------------
#define M_ROWS  32768           // B*N = 64*512
#define EMB     1024
#define NKP     17
#define APP_F   (EMB + NKP)     // 1041
#define ST_F    (4 + 3 * NKP)   // 55
#define KTOT    (APP_F + ST_F)  // 1096
#define KC      64              // fp16 K elements per chunk (128B row)
#define KPAD    1152            // 18 * 64
#define NCHUNK  (KPAD / KC)     // 18
#define TOK     1024

#define TILE_M  256
#define TILE_N  128
#define NMTILE  (M_ROWS / TILE_M)   // 128 (max; CTAs beyond n_act exit)
#define NNTILE  (TOK / TILE_N)      // 8

// Tiled-global + SMEM layout (pre-swizzled blobs):
//   A chunk tile: 256 rows x 128B = 32 KB;  B chunk tile: 128 rows x 128B = 16 KB
#define ROWB    128
#define A_TB    32768
#define B_TB    16384
#define STAGE_B (A_TB + B_TB)           // A | Bh = 49152
#define NSTAGE  4
#define SMEM_TOTAL (NSTAGE * STAGE_B)   // 196608 B (1 CTA/SM)

// ---------------------------------------------------------------------------
// Device scratch (static globals — no allocation). A is stored COMPACTED
// (active rows only, in scan order), tiled + pre-swizzled.
// ---------------------------------------------------------------------------
__device__ __half g_Ah[(size_t)M_ROWS * KPAD];   // compact slots; tail stays 0
__device__ __half g_Bh[(size_t)TOK * KPAD];
__device__ float  g_bias[TOK];
__device__ int    g_cidx[M_ROWS];                // row -> compact idx (or -1)
__device__ int    g_rowmap[M_ROWS];              // compact idx -> row
__device__ int    g_nact;                        // number of active rows

// ---------------------------------------------------------------------------
// PTX helpers (proven set only: ldmatrix / mma.sync / cp.async)
// ---------------------------------------------------------------------------
__device__ __forceinline__ uint32_t smem_u32(const void* p) {
    uint32_t a;
    asm("{ .reg .u64 t; cvta.to.shared.u64 t, %1; cvt.u32.u64 %0, t; }" : "=r"(a) : "l"(p));
    return a;
}

__device__ __forceinline__ void ldmx4(uint32_t* r, uint32_t addr) {
    asm volatile("ldmatrix.sync.aligned.m8n8.x4.shared.b16 {%0,%1,%2,%3}, [%4];"
                 : "=r"(r[0]), "=r"(r[1]), "=r"(r[2]), "=r"(r[3]) : "r"(addr));
}

__device__ __forceinline__ void mma16816(float* c, const uint32_t* a, const uint32_t* b) {
    asm volatile(
        "mma.sync.aligned.m16n8k16.row.col.f32.f16.f16.f32 "
        "{%0,%1,%2,%3}, {%4,%5,%6,%7}, {%8,%9}, {%0,%1,%2,%3};"
        : "+f"(c[0]), "+f"(c[1]), "+f"(c[2]), "+f"(c[3])
        : "r"(a[0]), "r"(a[1]), "r"(a[2]), "r"(a[3]), "r"(b[0]), "r"(b[1]));
}

__device__ __forceinline__ void cp16(uint32_t dst, const void* src) {
    asm volatile("cp.async.cg.shared.global [%0], [%1], 16;" :: "r"(dst), "l"(src) : "memory");
}
__device__ __forceinline__ void cp_commit() {
    asm volatile("cp.async.commit_group;" ::: "memory");
}
template <int N>
__device__ __forceinline__ void cp_wait() {
    asm volatile("cp.async.wait_group %0;" :: "n"(N) : "memory");
}

// Swizzle: 16B chunk index within a 128B row, XORed with (row & 7).
__device__ __forceinline__ uint32_t sw_off(uint32_t row, uint32_t c16) {
    return row * ROWB + ((c16 ^ (row & 7u)) << 4);
}

// ---------------------------------------------------------------------------
// Scan: deterministic exclusive prefix sum over the mask -> compaction maps.
// ONE block, 1024 threads, 32 rows/thread.
// ---------------------------------------------------------------------------
__global__ void scan_mask(const unsigned int* __restrict__ mask)
{
    const int t = threadIdx.x;
    const int lane = t & 31, w = t >> 5;
    const int base = t * 32;

    int cnt = 0;
    #pragma unroll
    for (int i = 0; i < 32; i++) cnt += (mask[base + i] != 0u) ? 1 : 0;

    // inclusive scan across 1024 threads
    int x = cnt;
    #pragma unroll
    for (int d = 1; d < 32; d <<= 1) {
        int y = __shfl_up_sync(0xFFFFFFFFu, x, d);
        if (lane >= d) x += y;
    }
    __shared__ int wsum[32];
    if (lane == 31) wsum[w] = x;
    __syncthreads();
    if (w == 0) {
        int v = wsum[lane];
        #pragma unroll
        for (int d = 1; d < 32; d <<= 1) {
            int y = __shfl_up_sync(0xFFFFFFFFu, v, d);
            if (lane >= d) v += y;
        }
        wsum[lane] = v;
    }
    __syncthreads();

    int off = (x - cnt) + (w > 0 ? wsum[w - 1] : 0);   // exclusive prefix
    for (int i = 0; i < 32; i++) {
        const int r = base + i;
        if (mask[r] != 0u) { g_cidx[r] = off; g_rowmap[off] = r; off++; }
        else                 g_cidx[r] = -1;
    }
    if (t == 1023) g_nact = off;
}

// ---------------------------------------------------------------------------
// Fused prologue. Blocks [0, M_ROWS): active rows -> compact A slot (tiled,
// pre-swizzled); masked rows -> zero their 4 KB output row directly.
// Blocks [M_ROWS, +TOK): weight row -> g_Bh slots + fused bias.
// ---------------------------------------------------------------------------
__global__ void prep_all(const float* __restrict__ emb, const float* __restrict__ vis,
                         const float* __restrict__ bbox, const float* __restrict__ kp,
                         const float* __restrict__ app_W, const float* __restrict__ app_b,
                         const float* __restrict__ st_W, const float* __restrict__ st_b,
                         float* __restrict__ out)
{
    const int blk = blockIdx.x;
    const int tid = threadIdx.x;
    char* const AhB = reinterpret_cast<char*>(g_Ah);
    char* const BhB = reinterpret_cast<char*>(g_Bh);

    if (blk < M_ROWS) {
        const int r = blk;
        const int cidx = g_cidx[r];
        if (cidx < 0) {
            // masked row: output is exactly zero (no bias)
            const float4 z = make_float4(0.f, 0.f, 0.f, 0.f);
            float4* o = reinterpret_cast<float4*>(out + (size_t)r * TOK) + tid * 2;
            o[0] = z; o[1] = z;
            return;
        }
        const int mtile = cidx >> 8, mrow = cidx & 255;   // 256-row compact A tiles
        const size_t tb0 = (size_t)mtile * NCHUNK * A_TB;
        // Embedding: thread t packs halfs [8t, 8t+8) -> one swizzled 16B slot
        const float4* s = reinterpret_cast<const float4*>(emb + (size_t)r * EMB + tid * 8);
        float4 v0 = s[0], v1 = s[1];
        __half2 h0 = __floats2half2_rn(v0.x, v0.y);
        __half2 h1 = __floats2half2_rn(v0.z, v0.w);
        __half2 h2 = __floats2half2_rn(v1.x, v1.y);
        __half2 h3 = __floats2half2_rn(v1.z, v1.w);
        uint4 pk;
        pk.x = *reinterpret_cast<uint32_t*>(&h0);
        pk.y = *reinterpret_cast<uint32_t*>(&h1);
        pk.z = *reinterpret_cast<uint32_t*>(&h2);
        pk.w = *reinterpret_cast<uint32_t*>(&h3);
        const int c = tid >> 3;                         // chunk = (8t)/64
        const uint32_t c16 = (uint32_t)(tid & 7);
        *reinterpret_cast<uint4*>(AhB + tb0 + (size_t)c * A_TB
                                  + sw_off((uint32_t)mrow, c16)) = pk;
        // Tail: k in [1024, 1152), one half per thread
        const int k = EMB + tid;
        float v = 0.0f;
        if (k < APP_F)          v = vis[(size_t)r * NKP + (k - EMB)];
        else if (k < APP_F + 4) v = bbox[(size_t)r * 4 + (k - APP_F)];
        else if (k < KTOT)      v = kp[(size_t)r * (3 * NKP) + (k - APP_F - 4)];
        const int ct = k >> 6, kc = k & 63;
        *reinterpret_cast<__half*>(AhB + tb0 + (size_t)ct * A_TB
                                   + sw_off((uint32_t)mrow, (uint32_t)(kc >> 3))
                                   + (kc & 7) * 2) = __float2half_rn(v);
    } else {
        const int t = blk - M_ROWS;
        const int ntile = t >> 7, nrow = t & 127;       // 128-row B tiles
        const size_t tb0 = (size_t)ntile * NCHUNK * B_TB;
        if (tid == 0) g_bias[t] = app_b[t] + st_b[t];
        for (int k = tid; k < KPAD; k += 128) {
            float v = 0.0f;
            if (k < APP_F)      v = app_W[t * APP_F + k];
            else if (k < KTOT)  v = st_W[t * ST_F + (k - APP_F)];
            const int c = k >> 6, kc = k & 63;
            *reinterpret_cast<__half*>(BhB + tb0 + (size_t)c * B_TB
                                       + sw_off((uint32_t)nrow, (uint32_t)(kc >> 3))
                                       + (kc & 7) * 2) = __float2half_rn(v);
        }
    }
}

// ---------------------------------------------------------------------------
// Main GEMM over COMPACTED A rows: fp16 x fp16 -> fp32 accumulate.
// 256x128 CTA tile, 512 threads, 16 warps (64x32 warp tile, 4x4 warp grid).
// CTAs whose compact row range is beyond n_act exit immediately.
// Epilogue scatters through g_rowmap; all computed rows are active (bias on).
// ---------------------------------------------------------------------------
__global__ void __launch_bounds__(512, 1)
gemm_hmma(float* __restrict__ out)
{
    const int nact = g_nact;
    const int row0 = blockIdx.y * TILE_M;
    if (row0 >= nact) return;           // nothing in this compact tile

    extern __shared__ __align__(128) char smem[];
    const uint32_t sb = smem_u32(smem);

    const int tid    = threadIdx.x;
    const int lane   = tid & 31;
    const int wid    = tid >> 5;
    const int warp_m = (wid & 3) * 64;      // 4 warps along M
    const int warp_n = (wid >> 2) * 32;     // 4 warps along N
    const int col0   = blockIdx.x * TILE_N;

    const char* const pA  = reinterpret_cast<const char*>(g_Ah)
                          + (size_t)blockIdx.y * NCHUNK * A_TB;
    const char* const pBh = reinterpret_cast<const char*>(g_Bh)
                          + (size_t)blockIdx.x * NCHUNK * B_TB;

    float acc[4][4][4];
    #pragma unroll
    for (int i = 0; i < 4; i++)
        #pragma unroll
        for (int j = 0; j < 4; j++)
            #pragma unroll
            for (int q = 0; q < 4; q++) acc[i][j][q] = 0.0f;

    // ---- async-load one 64-deep K chunk: contiguous copy, dst_off == src_off
    auto cpAll = [&](int s, uint32_t buf) {
        {
            const char* sa = pA + (size_t)s * A_TB + tid * 64;
            const uint32_t da = buf + (uint32_t)tid * 64;
            #pragma unroll
            for (int i = 0; i < 4; i++) cp16(da + i * 16, sa + i * 16);
        }
        {
            const char* sh = pBh + (size_t)s * B_TB + tid * 32;
            const uint32_t dh = buf + A_TB + (uint32_t)tid * 32;
            cp16(dh, sh); cp16(dh + 16, sh + 16);
        }
    };

    // ---- compute one 64-deep K chunk
    auto compute = [&](uint32_t buf) {
        const uint32_t aH = buf;
        const uint32_t bH = buf + A_TB;
        const uint32_t arow = (uint32_t)(lane & 15);
        const uint32_t nrow = (uint32_t)((lane & 7) + ((lane >> 4) << 3));
        #pragma unroll
        for (int k16 = 0; k16 < 4; k16++) {
            const uint32_t ac = (uint32_t)(k16 * 2 + (lane >> 4));
            const uint32_t bc = (uint32_t)(k16 * 2 + ((lane & 8) >> 3));
            uint32_t Ah[4][4], Bh[4][2];
            #pragma unroll
            for (int am = 0; am < 4; am++)
                ldmx4(Ah[am], aH + sw_off((uint32_t)(warp_m + am * 16) + arow, ac));
            #pragma unroll
            for (int bp = 0; bp < 2; bp++) {
                const uint32_t ro = sw_off((uint32_t)(warp_n + bp * 16) + nrow, bc);
                uint32_t r[4];
                ldmx4(r, bH + ro);
                Bh[bp*2][0]=r[0]; Bh[bp*2][1]=r[1]; Bh[bp*2+1][0]=r[2]; Bh[bp*2+1][1]=r[3];
            }
            #pragma unroll
            for (int am = 0; am < 4; am++)
                #pragma unroll
                for (int an = 0; an < 4; an++)
                    mma16816(acc[am][an], Ah[am], Bh[an]);
        }
    };

    // ---- 4-stage pipeline, prefetch distance 3, single barrier per chunk.
    cpAll(0, sb + 0 * STAGE_B); cp_commit();
    cpAll(1, sb + 1 * STAGE_B); cp_commit();
    cpAll(2, sb + 2 * STAGE_B); cp_commit();

    for (int s = 0; s < NCHUNK; s++) {
        cp_wait<2>();           // groups are 1-per-iter (empty ones too): chunk s done
        __syncthreads();        // all warps finished compute(s-1) -> stage (s-1)%4 free
        if (s + 3 < NCHUNK)
            cpAll(s + 3, sb + (uint32_t)((s + 3) % NSTAGE) * STAGE_B);
        cp_commit();            // unconditional: keeps outstanding-group count invariant
        compute(sb + (uint32_t)(s % NSTAGE) * STAGE_B);
    }

    // ---- epilogue: scatter via rowmap, bias always (rows are active)
    #pragma unroll
    for (int am = 0; am < 4; am++) {
        const int c1 = row0 + warp_m + am * 16 + (lane >> 2);
        const int c2 = c1 + 8;
        const bool ok1 = (c1 < nact);
        const bool ok2 = (c2 < nact);
        const int r1 = ok1 ? g_rowmap[c1] : 0;
        const int r2 = ok2 ? g_rowmap[c2] : 0;
        #pragma unroll
        for (int an = 0; an < 4; an++) {
            const int cc = col0 + warp_n + an * 8 + 2 * (lane & 3);
            const float b0 = g_bias[cc], b1 = g_bias[cc + 1];
            if (ok1) {
                float2 v; v.x = acc[am][an][0] + b0; v.y = acc[am][an][1] + b1;
                *reinterpret_cast<float2*>(out + (size_t)r1 * TOK + cc) = v;
            }
            if (ok2) {
                float2 v; v.x = acc[am][an][2] + b0; v.y = acc[am][an][3] + b1;
                *reinterpret_cast<float2*>(out + (size_t)r2 * TOK + cc) = v;
            }
        }
    }
}

// ---------------------------------------------------------------------------
extern "C" void kernel_launch(void* const* d_in, const int* in_sizes, int n_in,
                              void* d_out, int out_size)
{
    const float*        emb   = (const float*)d_in[0];
    const float*        vis   = (const float*)d_in[1];
    const float*        bbox  = (const float*)d_in[2];
    const float*        kp    = (const float*)d_in[3];
    const unsigned int* mask  = (const unsigned int*)d_in[4];
    const float*        app_W = (const float*)d_in[5];
    const float*        app_b = (const float*)d_in[6];
    const float*        st_W  = (const float*)d_in[7];
    const float*        st_b  = (const float*)d_in[8];
    float*              out   = (float*)d_out;

    cudaFuncSetAttribute(gemm_hmma, cudaFuncAttributeMaxDynamicSharedMemorySize, SMEM_TOTAL);

    scan_mask<<<1, 1024>>>(mask);
    prep_all<<<M_ROWS + TOK, 128>>>(emb, vis, bbox, kp, app_W, app_b, st_W, st_b, out);

    dim3 grid(NNTILE, NMTILE);   // (8, 128 max); CTAs past n_act exit instantly
    gemm_hmma<<<grid, 512, SMEM_TOTAL>>>(out);
}